// round 15
// baseline (speedup 1.0000x reference)
#include <cuda_runtime.h>
#include <math.h>
#include <stdint.h>

// Problem constants (fixed by setup_inputs)
#define Bb 2
#define Cc 6
#define Nn 8192
#define Dd 256
#define HF 64
#define WF 64
#define ROWS (Bb*Nn)   // 16384

// ---------------- scratch (device globals; no allocs allowed) ----------------
__device__ float g_ApT[Dd*Dd];    // ApT[e][f] = ln_g[f] * sum_d kv_w[e,d]*q_w[f,d]
__device__ float g_W2T[Dd*Dd];    // W2T[g][d] = sum_e out_w[e,g]*kv_w[d,256+e]
__device__ float g_owT[Dd*Dd];    // out_w transposed: owT[g][e] = out_w[e][g]
__device__ float g_S[Dd];         // S[e] = sum_d kv_w[e,d]*t[d]
__device__ float g_cp[Dd];        // cp[e] = sum_d qb2[d]*kv_w[e,d]
__device__ float g_qb2[Dd];       // q_b + ln_b @ q_w
__device__ float g_t[Dd];         // t[d] = sum_f ln_g[f]*q_w[f,d]
__device__ float g_b2[Dd];        // kv_b[D:] @ out_w
__device__ float g_mu[ROWS];
__device__ float g_rstd[ROWS];
__device__ float g_qk[ROWS*Dd];
__device__ float g_sbar[ROWS*Dd];
__device__ float g_asum[ROWS];

// ---------------- baseline-ISA helpers (no sm_103a features) ------------------
__device__ __forceinline__ uint32_t f2tf(float f) {
    uint32_t r;
    asm("cvt.rna.tf32.f32 %0, %1;" : "=r"(r) : "f"(f));
    return r;
}
__device__ __forceinline__ void cp16(uint32_t saddr, const void* gp) {
    asm volatile("cp.async.cg.shared.global [%0], [%1], 16;" :: "r"(saddr), "l"(gp));
}
#define CP_COMMIT() asm volatile("cp.async.commit_group;" ::: "memory")
#define CP_WAIT1()  asm volatile("cp.async.wait_group 1;" ::: "memory")
#define CP_WAIT0()  asm volatile("cp.async.wait_group 0;" ::: "memory")

__device__ __forceinline__ void mma_tf32(float& c0, float& c1, float& c2, float& c3,
                                         uint32_t a0, uint32_t a1, uint32_t a2, uint32_t a3,
                                         uint32_t b0, uint32_t b1) {
    asm volatile(
        "mma.sync.aligned.m16n8k8.row.col.f32.tf32.tf32.f32 "
        "{%0,%1,%2,%3}, {%4,%5,%6,%7}, {%8,%9}, {%0,%1,%2,%3};"
        : "+f"(c0), "+f"(c1), "+f"(c2), "+f"(c3)
        : "r"(a0), "r"(a1), "r"(a2), "r"(a3), "r"(b0), "r"(b1));
}

// ---------------- tensor-core GEMM via mma.sync (tf32) ------------------------
// Y[M,256] = X[M,256(ldx)] @ BT^T  (BT: [256 n][K=256] K-major, row stride ldb)
// MODE 0: Y = acc
// MODE 1: Y = rstd[r]*(acc - mu[r]*S[c]) + cp[c]
// MODE 2: Y = resid[r,c] + acc + asum[r]*b2[c] + e1[c]
// MODE 3: Y = acc * e1[c]                      (column scale)
#define KPAD 36
#define BUFSZ (128 * KPAD)                 // floats per buffer (A or B)
#define GEMM_SMEM_BYTES (4 * BUFSZ * 4)    // A[2] + B[2]

template<int MODE>
__global__ __launch_bounds__(256, 2)
void gemm_mma(const float* __restrict__ X, int ldx,
              const float* __restrict__ BT, int ldb,
              float* __restrict__ Y,
              const float* __restrict__ resid,
              const float* __restrict__ e1)
{
    extern __shared__ float smbuf[];
    float* Abuf = smbuf;                 // [2][128][KPAD]
    float* Bbuf = smbuf + 2 * BUFSZ;     // [2][128][KPAD]

    const int tid  = threadIdx.x;
    const int lane = tid & 31;
    const int wrp  = tid >> 5;      // 0..7
    const int wm   = wrp >> 1;      // 0..3  -> warp M offset wm*32
    const int wn   = wrp & 1;       // 0..1  -> warp N offset wn*64
    const int g    = lane >> 2;     // 0..7
    const int tg   = lane & 3;      // 0..3

    const int m0 = blockIdx.x * 128;
    const int n0 = blockIdx.y * 128;

    const uint32_t sA = (uint32_t)__cvta_generic_to_shared(Abuf);
    const uint32_t sB = (uint32_t)__cvta_generic_to_shared(Bbuf);

    float acc[2][8][4];
#pragma unroll
    for (int i = 0; i < 2; i++)
#pragma unroll
        for (int j = 0; j < 8; j++)
#pragma unroll
            for (int k = 0; k < 4; k++) acc[i][j][k] = 0.f;

    auto issue = [&](int kc, int buf) {
#pragma unroll
        for (int i = 0; i < 4; i++) {
            int j = tid + 256 * i;          // 0..1023
            int row = j >> 3, kq = j & 7;   // 128 rows x 8 float4
            uint32_t dst = (uint32_t)((buf * BUFSZ + row * KPAD + kq * 4) * 4);
            cp16(sA + dst, &X [(size_t)(m0 + row) * ldx + kc * 32 + kq * 4]);
            cp16(sB + dst, &BT[(size_t)(n0 + row) * ldb + kc * 32 + kq * 4]);
        }
    };

    issue(0, 0);
    CP_COMMIT();

    for (int kc = 0; kc < 8; kc++) {
        if (kc + 1 < 8) { issue(kc + 1, (kc + 1) & 1); CP_COMMIT(); }
        if (kc + 1 < 8) CP_WAIT1(); else CP_WAIT0();
        __syncthreads();

        const float* Asm = Abuf + (kc & 1) * BUFSZ;
        const float* Bsm = Bbuf + (kc & 1) * BUFSZ;

#pragma unroll
        for (int ks = 0; ks < 4; ks++) {
            uint32_t afr[2][4];
#pragma unroll
            for (int mt = 0; mt < 2; mt++) {
                int rbase = wm * 32 + mt * 16;
                afr[mt][0] = f2tf(Asm[(rbase + g    ) * KPAD + ks * 8 + tg    ]);
                afr[mt][1] = f2tf(Asm[(rbase + g + 8) * KPAD + ks * 8 + tg    ]);
                afr[mt][2] = f2tf(Asm[(rbase + g    ) * KPAD + ks * 8 + tg + 4]);
                afr[mt][3] = f2tf(Asm[(rbase + g + 8) * KPAD + ks * 8 + tg + 4]);
            }
#pragma unroll
            for (int nt = 0; nt < 8; nt++) {
                int nbase = wn * 64 + nt * 8;
                uint32_t b0 = f2tf(Bsm[(nbase + g) * KPAD + ks * 8 + tg    ]);
                uint32_t b1 = f2tf(Bsm[(nbase + g) * KPAD + ks * 8 + tg + 4]);
                mma_tf32(acc[0][nt][0], acc[0][nt][1], acc[0][nt][2], acc[0][nt][3],
                         afr[0][0], afr[0][1], afr[0][2], afr[0][3], b0, b1);
                mma_tf32(acc[1][nt][0], acc[1][nt][1], acc[1][nt][2], acc[1][nt][3],
                         afr[1][0], afr[1][1], afr[1][2], afr[1][3], b0, b1);
            }
        }
        __syncthreads();
    }

    // ---- epilogue ----
#pragma unroll
    for (int mt = 0; mt < 2; mt++) {
        int rA = m0 + wm * 32 + mt * 16 + g;     // rows rA and rA+8
        int rB = rA + 8;
        float p0a = 0.f, p1a = 0.f, p0b = 0.f, p1b = 0.f;
        if (MODE == 1) {
            p0a = g_rstd[rA]; p1a = g_mu[rA];
            p0b = g_rstd[rB]; p1b = g_mu[rB];
        } else if (MODE == 2) {
            p0a = g_asum[rA];
            p0b = g_asum[rB];
        }
#pragma unroll
        for (int nt = 0; nt < 8; nt++) {
            int c0 = n0 + wn * 64 + nt * 8 + 2 * tg;
            float2 o0, o1;
            if (MODE == 0) {
                o0.x = acc[mt][nt][0]; o0.y = acc[mt][nt][1];
                o1.x = acc[mt][nt][2]; o1.y = acc[mt][nt][3];
            } else if (MODE == 3) {
                float2 e1v = *reinterpret_cast<const float2*>(&e1[c0]);
                o0.x = acc[mt][nt][0] * e1v.x; o0.y = acc[mt][nt][1] * e1v.y;
                o1.x = acc[mt][nt][2] * e1v.x; o1.y = acc[mt][nt][3] * e1v.y;
            } else if (MODE == 1) {
                float2 Sv  = *reinterpret_cast<const float2*>(&g_S[c0]);
                float2 cpv = *reinterpret_cast<const float2*>(&g_cp[c0]);
                o0.x = p0a * (acc[mt][nt][0] - p1a * Sv.x) + cpv.x;
                o0.y = p0a * (acc[mt][nt][1] - p1a * Sv.y) + cpv.y;
                o1.x = p0b * (acc[mt][nt][2] - p1b * Sv.x) + cpv.x;
                o1.y = p0b * (acc[mt][nt][3] - p1b * Sv.y) + cpv.y;
            } else {
                float2 b2v = *reinterpret_cast<const float2*>(&g_b2[c0]);
                float2 e1v = *reinterpret_cast<const float2*>(&e1[c0]);
                float2 r0  = *reinterpret_cast<const float2*>(&resid[(size_t)rA * 256 + c0]);
                float2 r1  = *reinterpret_cast<const float2*>(&resid[(size_t)rB * 256 + c0]);
                o0.x = r0.x + acc[mt][nt][0] + p0a * b2v.x + e1v.x;
                o0.y = r0.y + acc[mt][nt][1] + p0a * b2v.y + e1v.y;
                o1.x = r1.x + acc[mt][nt][2] + p0b * b2v.x + e1v.x;
                o1.y = r1.y + acc[mt][nt][3] + p0b * b2v.y + e1v.y;
            }
            *reinterpret_cast<float2*>(&Y[(size_t)rA * 256 + c0]) = o0;
            *reinterpret_cast<float2*>(&Y[(size_t)rB * 256 + c0]) = o1;
        }
    }
}

// ---------------- K1: fused transpose(out_w) + qb2/t + b2 ----------------------
__global__ void prep1_k(const float* __restrict__ out_w,
                        const float* __restrict__ q_w,  const float* __restrict__ q_b,
                        const float* __restrict__ ln_b, const float* __restrict__ ln_g,
                        const float* __restrict__ kv_b) {
    int blk = blockIdx.x;
    int tid = threadIdx.x;
    if (blk < 64) {
        __shared__ float tbuf[32][33];
        int bx = blk & 7, by = blk >> 3;
        int tx = tid & 31, ty = tid >> 5;   // 32 x 8
#pragma unroll
        for (int i = 0; i < 32; i += 8)
            tbuf[ty + i][tx] = out_w[(size_t)(by * 32 + ty + i) * Dd + bx * 32 + tx];
        __syncthreads();
#pragma unroll
        for (int i = 0; i < 32; i += 8)
            g_owT[(size_t)(bx * 32 + ty + i) * Dd + by * 32 + tx] = tbuf[tx][ty + i];
    } else if (blk == 64) {
        int d = tid;
        float sq = q_b[d], st = 0.f;
        for (int f = 0; f < Dd; f++) {
            float a = q_w[f * Dd + d];
            sq = fmaf(ln_b[f], a, sq);
            st = fmaf(ln_g[f], a, st);
        }
        g_qb2[d] = sq;
        g_t[d]   = st;
    } else {
        int gcol = tid;
        float s = 0.f;
        for (int e = 0; e < Dd; e++) s = fmaf(kv_b[Dd + e], out_w[e * Dd + gcol], s);
        g_b2[gcol] = s;
    }
}

// ---------------- K2: fused cp + S (one pass over kv_w rows) -------------------
__global__ void prep2_k(const float* __restrict__ kv_w) {
    int w = threadIdx.x >> 5, lane = threadIdx.x & 31;
    int e = blockIdx.x * 8 + w;
    const float* rowp = kv_w + (size_t)e * (2 * Dd);
    float scp = 0.f, sS = 0.f;
#pragma unroll
    for (int d = lane; d < Dd; d += 32) {
        float v = rowp[d];
        scp = fmaf(g_qb2[d], v, scp);
        sS  = fmaf(g_t[d],   v, sS);
    }
    for (int o = 16; o; o >>= 1) {
        scp += __shfl_xor_sync(0xffffffffu, scp, o);
        sS  += __shfl_xor_sync(0xffffffffu, sS,  o);
    }
    if (lane == 0) { g_cp[e] = scp; g_S[e] = sS; }
}

// ---------------- LN row stats ------------------------------------------------
__global__ void row_stats_k(const float* __restrict__ X) {
    int row = blockIdx.x * 8 + (threadIdx.x >> 5);
    int lane = threadIdx.x & 31;
    const float4* xr = reinterpret_cast<const float4*>(X + (size_t)row * Dd);
    float s = 0.f, ss = 0.f;
#pragma unroll
    for (int i = lane; i < Dd / 4; i += 32) {
        float4 v = xr[i];
        s  += v.x + v.y + v.z + v.w;
        ss += v.x * v.x + v.y * v.y + v.z * v.z + v.w * v.w;
    }
    for (int o = 16; o; o >>= 1) {
        s  += __shfl_xor_sync(0xffffffffu, s, o);
        ss += __shfl_xor_sync(0xffffffffu, ss, o);
    }
    if (lane == 0) {
        float mu  = s * (1.f / Dd);
        float var = ss * (1.f / Dd) - mu * mu;
        g_mu[row]   = mu;
        g_rstd[row] = rsqrtf(var + 1e-5f);
    }
}

// ---------------- fused sample + logits + softmax + aggregate -----------------
__global__ void sample_k(const float* __restrict__ feat,    // (B*C, 64, 64, 256)
                         const float* __restrict__ coords,  // (B, C, N, 2)
                         const int*   __restrict__ valid)   // (B, C, N) int32
{
    int row = blockIdx.x;          // b*N + n
    int b = row >> 13;
    int n = row & (Nn - 1);
    int t = threadIdx.x;           // 128 threads, 2 channels each

    __shared__ float s_dot[Cc];
    __shared__ float s_red[4][Cc];
    __shared__ int   s_valid[Cc];

    float2 qk2 = *reinterpret_cast<const float2*>(&g_qk[(size_t)row * Dd + t * 2]);

    if (t < Cc) s_valid[t] = valid[((size_t)(b * Cc + t)) * Nn + n];

    float sxv[Cc], syv[Cc], part[Cc];
#pragma unroll
    for (int c = 0; c < Cc; c++) {
        const float* fb = feat + ((size_t)(b * Cc + c)) * (HF * WF * Dd);
        float2 pc = *reinterpret_cast<const float2*>(
            &coords[(((size_t)(b * Cc + c)) * Nn + n) * 2]);
        float x = (pc.x + 1.f) * 0.5f * (WF - 1);
        float y = (pc.y + 1.f) * 0.5f * (HF - 1);
        float x0f = floorf(x), y0f = floorf(y);
        float wx1 = x - x0f, wx0 = 1.f - wx1;
        float wy1 = y - y0f, wy0 = 1.f - wy1;
        float x1f = x0f + 1.f, y1f = y0f + 1.f;
        bool bx0 = (x0f >= 0.f) && (x0f <= (float)(WF - 1));
        bool bx1 = (x1f >= 0.f) && (x1f <= (float)(WF - 1));
        bool by0 = (y0f >= 0.f) && (y0f <= (float)(HF - 1));
        bool by1 = (y1f >= 0.f) && (y1f <= (float)(HF - 1));
        int cx0 = min(max((int)x0f, 0), WF - 1);
        int cx1 = min(max((int)x1f, 0), WF - 1);
        int cy0 = min(max((int)y0f, 0), HF - 1);
        int cy1 = min(max((int)y1f, 0), HF - 1);
        float w00 = wy0 * wx0 * ((by0 && bx0) ? 1.f : 0.f);
        float w01 = wy0 * wx1 * ((by0 && bx1) ? 1.f : 0.f);
        float w10 = wy1 * wx0 * ((by1 && bx0) ? 1.f : 0.f);
        float w11 = wy1 * wx1 * ((by1 && bx1) ? 1.f : 0.f);
        const float2* f00 = reinterpret_cast<const float2*>(fb + (size_t)(cy0 * WF + cx0) * Dd) + t;
        const float2* f01 = reinterpret_cast<const float2*>(fb + (size_t)(cy0 * WF + cx1) * Dd) + t;
        const float2* f10 = reinterpret_cast<const float2*>(fb + (size_t)(cy1 * WF + cx0) * Dd) + t;
        const float2* f11 = reinterpret_cast<const float2*>(fb + (size_t)(cy1 * WF + cx1) * Dd) + t;
        float2 v00 = *f00, v01 = *f01, v10 = *f10, v11 = *f11;
        float sx = w00 * v00.x + w01 * v01.x + w10 * v10.x + w11 * v11.x;
        float sy = w00 * v00.y + w01 * v01.y + w10 * v10.y + w11 * v11.y;
        sxv[c] = sx;
        syv[c] = sy;
        part[c] = sx * qk2.x + sy * qk2.y;
    }

    int lane = t & 31, w = t >> 5;
#pragma unroll
    for (int c = 0; c < Cc; c++) {
        float p = part[c];
        for (int o = 16; o; o >>= 1) p += __shfl_xor_sync(0xffffffffu, p, o);
        if (lane == 0) s_red[w][c] = p;
    }
    __syncthreads();
    if (t < Cc) {
        float d = s_red[0][t] + s_red[1][t] + s_red[2][t] + s_red[3][t];
        s_dot[t] = d * 0.0625f;   // 1/sqrt(256)
    }
    __syncthreads();

    float lg[Cc];
    float mx = -1e30f;
#pragma unroll
    for (int c = 0; c < Cc; c++) {
        lg[c] = s_valid[c] ? s_dot[c] : -1e30f;
        mx = fmaxf(mx, lg[c]);
    }
    float ex[Cc]; float ssum = 0.f;
#pragma unroll
    for (int c = 0; c < Cc; c++) {
        ex[c] = s_valid[c] ? expf(lg[c] - mx) : 0.f;
        ssum += ex[c];
    }
    float inv = (ssum == 0.f) ? 0.f : 1.f / ssum;
    float sbx = 0.f, sby = 0.f;
#pragma unroll
    for (int c = 0; c < Cc; c++) {
        float a = ex[c] * inv;
        sbx = fmaf(a, sxv[c], sbx);
        sby = fmaf(a, syv[c], sby);
    }
    *reinterpret_cast<float2*>(&g_sbar[(size_t)row * Dd + t * 2]) = make_float2(sbx, sby);
    if (t == 0) g_asum[row] = (ssum == 0.f) ? 0.f : 1.f;
}

// ---------------- launch ------------------------------------------------------
extern "C" void kernel_launch(void* const* d_in, const int* in_sizes, int n_in,
                              void* d_out, int out_size) {
    const float* queries = (const float*)d_in[0];
    const float* feat    = (const float*)d_in[1];
    const float* coords  = (const float*)d_in[2];
    const int*   valid   = (const int*)d_in[3];
    const float* q_w   = (const float*)d_in[4];
    const float* q_b   = (const float*)d_in[5];
    const float* kv_w  = (const float*)d_in[6];
    const float* kv_b  = (const float*)d_in[7];
    const float* out_w = (const float*)d_in[8];
    const float* out_b = (const float*)d_in[9];
    const float* ln_g  = (const float*)d_in[10];
    const float* ln_b  = (const float*)d_in[11];
    float* out = (float*)d_out;

    float *pApT, *pW2T, *powT, *pqk, *psbar;
    cudaGetSymbolAddress((void**)&pApT,  g_ApT);
    cudaGetSymbolAddress((void**)&pW2T,  g_W2T);
    cudaGetSymbolAddress((void**)&powT,  g_owT);
    cudaGetSymbolAddress((void**)&pqk,   g_qk);
    cudaGetSymbolAddress((void**)&psbar, g_sbar);

    cudaFuncSetAttribute(gemm_mma<0>, cudaFuncAttributeMaxDynamicSharedMemorySize, GEMM_SMEM_BYTES);
    cudaFuncSetAttribute(gemm_mma<1>, cudaFuncAttributeMaxDynamicSharedMemorySize, GEMM_SMEM_BYTES);
    cudaFuncSetAttribute(gemm_mma<2>, cudaFuncAttributeMaxDynamicSharedMemorySize, GEMM_SMEM_BYTES);
    cudaFuncSetAttribute(gemm_mma<3>, cudaFuncAttributeMaxDynamicSharedMemorySize, GEMM_SMEM_BYTES);

    // Fused precompute
    prep1_k<<<66, 256>>>(out_w, q_w, q_b, ln_b, ln_g, kv_b);
    prep2_k<<<32, 256>>>(kv_w);
    // ApT[e][f] = ln_g[f] * sum_d kv_w[e,d]*q_w[f,d]
    gemm_mma<3><<<dim3(2, 2), 256, GEMM_SMEM_BYTES>>>(kv_w, 2 * Dd, q_w, Dd, pApT, nullptr, ln_g);
    // W2T[g][d] = sum_e owT[g,e]*kv_w[d,256+e]
    gemm_mma<0><<<dim3(2, 2), 256, GEMM_SMEM_BYTES>>>(powT, Dd, kv_w + Dd, 2 * Dd, pW2T, nullptr, nullptr);

    // LN stats
    row_stats_k<<<ROWS / 8, 256>>>(queries);

    // qk = rstd*(queries @ A' - mu*S) + cp    (tf32 mma.sync)
    gemm_mma<1><<<dim3(ROWS / 128, 2), 256, GEMM_SMEM_BYTES>>>(queries, Dd, pApT, Dd, pqk, nullptr, nullptr);

    // sample + softmax + aggregate
    sample_k<<<ROWS, 128>>>(feat, coords, valid);

    // final = residual + sbar @ W2 + asum*b2 + out_b    (tf32 mma.sync)
    gemm_mma<2><<<dim3(ROWS / 128, 2), 256, GEMM_SMEM_BYTES>>>(psbar, Dd, pW2T, Dd, out, queries, out_b);
}